// round 5
// baseline (speedup 1.0000x reference)
#include <cuda_runtime.h>
#include <math.h>

#define NN   50000
#define EE   1600000
#define IND  256
#define HD   64
#define CD   16
#define NTR  5000
#define NH   (NN*HD)

// Scratch (no allocs allowed) — all 16B aligned for float4 access.
__device__ __align__(16) float g_t[NH];      // x @ W  (transformed features)
__device__ __align__(16) float g_h[NH];      // scatter accumulator / layer output
__device__ __align__(16) float g_hn[NH];     // L2-normalized h
__device__ float g_dinv[NN];                 // D^{-1/2} including self-loop
__device__ int   g_deg[NN];

// ---------------------------------------------------------------------------
__global__ void k_zero_f4(float4* p, int n4) {
    int i = blockIdx.x * blockDim.x + threadIdx.x;
    if (i < n4) p[i] = make_float4(0.f, 0.f, 0.f, 0.f);
}
__global__ void k_zero_i(int* p, int n) {
    int i = blockIdx.x * blockDim.x + threadIdx.x;
    if (i < n) p[i] = 0;
}
__global__ void k_deg(const int* __restrict__ dst) {
    int e = blockIdx.x * blockDim.x + threadIdx.x;
    if (e < EE) atomicAdd(&g_deg[dst[e]], 1);
}
__global__ void k_dinv() {
    int i = blockIdx.x * blockDim.x + threadIdx.x;
    if (i < NN) g_dinv[i] = rsqrtf((float)g_deg[i] + 1.0f);  // +1 self-loop
}

// ---------------------------------------------------------------------------
// O[N,64] = A[N,K] @ W[K,64].  64 threads/block, 8 rows/block, A tile in smem.
template <int K>
__global__ void k_gemm(const float* __restrict__ A, const float* __restrict__ W,
                       float* __restrict__ O) {
    __shared__ float sA[8][K];
    const int tx = threadIdx.x;           // output column 0..63
    const int rb = blockIdx.x * 8;
    for (int i = tx; i < 8 * K; i += 64) {
        int r = i / K, c = i - r * K;
        int row = rb + r;
        sA[r][c] = (row < NN) ? A[(size_t)row * K + c] : 0.0f;
    }
    __syncthreads();
    float acc[8] = {0.f, 0.f, 0.f, 0.f, 0.f, 0.f, 0.f, 0.f};
#pragma unroll 4
    for (int k = 0; k < K; k++) {
        float wv = W[k * HD + tx];
#pragma unroll
        for (int r = 0; r < 8; r++) acc[r] += sA[r][k] * wv;
    }
#pragma unroll
    for (int r = 0; r < 8; r++) {
        int row = rb + r;
        if (row < NN) O[(size_t)row * HD + tx] = acc[r];
    }
}

// ---------------------------------------------------------------------------
// Edge scatter: 16 threads per edge, one float4 RED each.
__global__ void k_scatter(const int* __restrict__ src, const int* __restrict__ dst,
                          const float* __restrict__ t, float* __restrict__ acc) {
    long long tid = (long long)blockIdx.x * blockDim.x + threadIdx.x;
    int e = (int)(tid >> 4);
    if (e >= EE) return;
    int q = (int)(tid & 15);
    int s = __ldg(src + e), d = __ldg(dst + e);
    float nrm = g_dinv[s] * g_dinv[d];
    float4 v = ((const float4*)(t + (size_t)s * HD))[q];
    v.x *= nrm; v.y *= nrm; v.z *= nrm; v.w *= nrm;
    atomicAdd(((float4*)(acc + (size_t)d * HD)) + q, v);
}

// Self-loop + bias (+relu):  acc = acc + dinv^2 * t + b
__global__ void k_final(const float* __restrict__ t, float* __restrict__ acc,
                        const float* __restrict__ b, int relu) {
    int i = blockIdx.x * blockDim.x + threadIdx.x;
    if (i >= NH) return;
    int n = i >> 6, j = i & 63;
    float di = g_dinv[n];
    float v = acc[i] + di * di * t[i] + b[j];
    if (relu) v = fmaxf(v, 0.0f);
    acc[i] = v;
}

// ---------------------------------------------------------------------------
// Row L2-normalize (thread per row) -> g_hn (aligned)
__global__ void k_norm(const float* __restrict__ h, float* __restrict__ oh) {
    int n = blockIdx.x * blockDim.x + threadIdx.x;
    if (n >= NN) return;
    const float4* hv = (const float4*)(h + (size_t)n * HD);
    float4 r[16];
    float ss = 0.f;
#pragma unroll
    for (int i = 0; i < 16; i++) {
        float4 v = hv[i];
        r[i] = v;
        ss += v.x * v.x + v.y * v.y + v.z * v.z + v.w * v.w;
    }
    float sc = 1.0f / fmaxf(sqrtf(ss), 1e-12f);
    float4* ov = (float4*)(oh + (size_t)n * HD);
#pragma unroll
    for (int i = 0; i < 16; i++) {
        float4 v = r[i];
        v.x *= sc; v.y *= sc; v.z *= sc; v.w *= sc;
        ov[i] = v;
    }
}

// Scalar coalesced copy (output view is only 4-byte aligned)
__global__ void k_copy(const float* __restrict__ in, float* __restrict__ out, int n) {
    int i = blockIdx.x * blockDim.x + threadIdx.x;
    if (i < n) out[i] = in[i];
}

// logits = hn @ W3 + b3 ; log_softmax (thread per row, W3 in smem)
__global__ void k_pred(const float* __restrict__ hn, const float* __restrict__ W3,
                       const float* __restrict__ b3, float* __restrict__ pred) {
    __shared__ float sW[HD * CD];
    __shared__ float sb[CD];
    for (int i = threadIdx.x; i < HD * CD; i += blockDim.x) sW[i] = W3[i];
    if (threadIdx.x < CD) sb[threadIdx.x] = b3[threadIdx.x];
    __syncthreads();
    int n = blockIdx.x * blockDim.x + threadIdx.x;
    if (n >= NN) return;
    float z[CD];
#pragma unroll
    for (int c = 0; c < CD; c++) z[c] = sb[c];
    const float4* hv = (const float4*)(hn + (size_t)n * HD);
#pragma unroll
    for (int k4 = 0; k4 < 16; k4++) {
        float4 v = hv[k4];
        const float* w0 = &sW[(k4 * 4 + 0) * CD];
        const float* w1 = &sW[(k4 * 4 + 1) * CD];
        const float* w2 = &sW[(k4 * 4 + 2) * CD];
        const float* w3 = &sW[(k4 * 4 + 3) * CD];
#pragma unroll
        for (int c = 0; c < CD; c++)
            z[c] += v.x * w0[c] + v.y * w1[c] + v.z * w2[c] + v.w * w3[c];
    }
    float m = z[0];
#pragma unroll
    for (int c = 1; c < CD; c++) m = fmaxf(m, z[c]);
    float se = 0.f;
#pragma unroll
    for (int c = 0; c < CD; c++) se += expf(z[c] - m);
    float lse = m + logf(se);
    float* po = pred + (size_t)n * CD;   // scalar stores: 4B alignment OK
#pragma unroll
    for (int c = 0; c < CD; c++) po[c] = z[c] - lse;
}

// NLL loss over train indices — single block, deterministic reduce
__global__ void k_loss(const float* __restrict__ pred, const int* __restrict__ labels,
                       const int* __restrict__ tidx, float* __restrict__ out) {
    __shared__ float sred[256];
    float s = 0.f;
    for (int i = threadIdx.x; i < NTR; i += 256) {
        int idx = tidx[i];
        s += pred[(size_t)idx * CD + labels[idx]];
    }
    sred[threadIdx.x] = s;
    __syncthreads();
    for (int o = 128; o > 0; o >>= 1) {
        if (threadIdx.x < o) sred[threadIdx.x] += sred[threadIdx.x + o];
        __syncthreads();
    }
    if (threadIdx.x == 0) out[0] = -sred[0] / (float)NTR;
}

// ---------------------------------------------------------------------------
extern "C" void kernel_launch(void* const* d_in, const int* in_sizes, int n_in,
                              void* d_out, int out_size) {
    const float* feats  = (const float*)d_in[0];
    const float* W1     = (const float*)d_in[1];
    const float* b1     = (const float*)d_in[2];
    const float* W2     = (const float*)d_in[3];
    const float* b2     = (const float*)d_in[4];
    const float* W3     = (const float*)d_in[5];
    const float* b3     = (const float*)d_in[6];
    const int*   edges  = (const int*)d_in[7];
    const int*   labels = (const int*)d_in[8];
    const int*   tidx   = (const int*)d_in[9];

    float* out      = (float*)d_out;
    float* out_pred = out + 1;
    float* out_h    = out + 1 + (size_t)NN * CD;

    float* t_ptr;  cudaGetSymbolAddress((void**)&t_ptr, g_t);
    float* h_ptr;  cudaGetSymbolAddress((void**)&h_ptr, g_h);
    float* hn_ptr; cudaGetSymbolAddress((void**)&hn_ptr, g_hn);
    int*   deg_ptr; cudaGetSymbolAddress((void**)&deg_ptr, g_deg);

    const int* src = edges;        // edge_list[0]
    const int* dst = edges + EE;   // edge_list[1]

    // degrees / normalization coefficients
    k_zero_i<<<(NN + 255) / 256, 256>>>(deg_ptr, NN);
    k_deg<<<(EE + 255) / 256, 256>>>(dst);
    k_dinv<<<(NN + 255) / 256, 256>>>();

    const int gemm_blocks = (NN + 7) / 8;
    const int zero_blocks = (NH / 4 + 255) / 256;
    long long sthreads = (long long)EE * 16;
    const int scat_blocks = (int)((sthreads + 255) / 256);
    const int elem_blocks = (NH + 255) / 256;

    // Layer 0: feats -> h0  (no relu)
    k_gemm<IND><<<gemm_blocks, 64>>>(feats, W1, t_ptr);
    k_zero_f4<<<zero_blocks, 256>>>((float4*)h_ptr, NH / 4);
    k_scatter<<<scat_blocks, 256>>>(src, dst, t_ptr, h_ptr);
    k_final<<<elem_blocks, 256>>>(t_ptr, h_ptr, b1, 0);

    // Hidden layers (relu)
    for (int l = 0; l < 2; l++) {
        k_gemm<HD><<<gemm_blocks, 64>>>(h_ptr, W2 + (size_t)l * HD * HD, t_ptr);
        k_zero_f4<<<zero_blocks, 256>>>((float4*)h_ptr, NH / 4);
        k_scatter<<<scat_blocks, 256>>>(src, dst, t_ptr, h_ptr);
        k_final<<<elem_blocks, 256>>>(t_ptr, h_ptr, b2 + (size_t)l * HD, 1);
    }

    // normalize -> g_hn ; copy to out_h ; logits + log_softmax -> out_pred ; nll -> out[0]
    k_norm<<<(NN + 255) / 256, 256>>>(h_ptr, hn_ptr);
    k_copy<<<elem_blocks, 256>>>(hn_ptr, out_h, NH);
    k_pred<<<(NN + 255) / 256, 256>>>(hn_ptr, W3, b3, out_pred);
    k_loss<<<1, 256>>>(out_pred, labels, tidx, out);
}

// round 6
// speedup vs baseline: 1.2266x; 1.2266x over previous
#include <cuda_runtime.h>
#include <math.h>

#define NN   50000
#define EE   1600000
#define IND  256
#define HD   64
#define CD   16
#define NTR  5000
#define NH   (NN*HD)

// Scratch (no allocs allowed) — all 16B aligned where float4-accessed.
__device__ __align__(16) float g_t[NH];        // x @ W  (transformed features)
__device__ __align__(16) float g_h[NH];        // layer output
__device__ __align__(16) float g_hn[NH];       // L2-normalized h
__device__ float g_dinv[NN];                   // D^{-1/2} including self-loop
__device__ int   g_deg[NN];                    // edge-only indegree
__device__ int   g_off[NN + 1];                // CSR offsets
__device__ int   g_cur[NN];                    // fill cursors
__device__ int   g_csr[EE];                    // src ids, grouped by dst
__device__ float g_enorm[EE];                  // dinv[src]*dinv[dst], CSR order

// ---------------------------------------------------------------------------
__global__ void k_zero_i(int* p, int n) {
    int i = blockIdx.x * blockDim.x + threadIdx.x;
    if (i < n) p[i] = 0;
}
__global__ void k_deg(const int* __restrict__ dst) {
    int e = blockIdx.x * blockDim.x + threadIdx.x;
    if (e < EE) atomicAdd(&g_deg[dst[e]], 1);
}
__global__ void k_dinv() {
    int i = blockIdx.x * blockDim.x + threadIdx.x;
    if (i < NN) g_dinv[i] = rsqrtf((float)g_deg[i] + 1.0f);  // +1 self-loop
}

// One-block prefix scan over degrees -> off, cur. 1024 threads, 49 elems each.
__global__ void k_scan() {
    __shared__ int ss[1024];
    const int CH = 49;
    int t = threadIdx.x;
    int base = t * CH;
    int s = 0;
    for (int i = 0; i < CH; i++) {
        int idx = base + i;
        if (idx < NN) s += g_deg[idx];
    }
    ss[t] = s;
    __syncthreads();
    int self = s;
    for (int o = 1; o < 1024; o <<= 1) {
        int v = (t >= o) ? ss[t - o] : 0;
        __syncthreads();
        ss[t] += v;
        __syncthreads();
    }
    int run = ss[t] - self;  // exclusive prefix
    for (int i = 0; i < CH; i++) {
        int idx = base + i;
        if (idx < NN) {
            g_off[idx] = run;
            g_cur[idx] = run;
            run += g_deg[idx];
        }
    }
    if (t == 1023) g_off[NN] = run;  // == EE
}

// Bucket edges by dst; store src id and precomputed symmetric norm.
__global__ void k_fill(const int* __restrict__ src, const int* __restrict__ dst) {
    int e = blockIdx.x * blockDim.x + threadIdx.x;
    if (e >= EE) return;
    int s = src[e], d = dst[e];
    int pos = atomicAdd(&g_cur[d], 1);
    g_csr[pos] = s;
    g_enorm[pos] = g_dinv[s] * g_dinv[d];
}

// ---------------------------------------------------------------------------
// O[N,64] = A[N,K] @ W[K,64].  128 threads, 16 rows/block, K chunked by 64.
// A chunk staged as float4 (broadcast LDS.128 reads), W chunk staged in smem.
template <int K>
__global__ void __launch_bounds__(128) k_gemm(const float* __restrict__ A,
                                              const float* __restrict__ W,
                                              float* __restrict__ O) {
    __shared__ float4 sA[16][16];   // 16 rows x 64 k-floats
    __shared__ float  sW[64][64];   // 64 k x 64 cols
    const int tx = threadIdx.x & 63;   // output column
    const int ty = threadIdx.x >> 6;   // row group (0/1)
    const int rb = blockIdx.x * 16;

    float acc[8] = {0.f, 0.f, 0.f, 0.f, 0.f, 0.f, 0.f, 0.f};

    for (int kc = 0; kc < K; kc += 64) {
        // stage A[rb..rb+15][kc..kc+63]
        for (int i = threadIdx.x; i < 256; i += 128) {
            int r = i >> 4, c4 = i & 15;
            int row = rb + r;
            sA[r][c4] = (row < NN)
                ? ((const float4*)(A + (size_t)row * K + kc))[c4]
                : make_float4(0.f, 0.f, 0.f, 0.f);
        }
        // stage W[kc..kc+63][0..63]  (contiguous 4096 floats)
        const float4* Wv = (const float4*)(W + (size_t)kc * HD);
        for (int i = threadIdx.x; i < 1024; i += 128) {
            ((float4*)&sW[0][0])[i] = Wv[i];
        }
        __syncthreads();
#pragma unroll
        for (int k4 = 0; k4 < 16; k4++) {
            float4 a[8];
#pragma unroll
            for (int r = 0; r < 8; r++) a[r] = sA[ty * 8 + r][k4];
            float w0 = sW[k4 * 4 + 0][tx];
            float w1 = sW[k4 * 4 + 1][tx];
            float w2 = sW[k4 * 4 + 2][tx];
            float w3 = sW[k4 * 4 + 3][tx];
#pragma unroll
            for (int r = 0; r < 8; r++) {
                acc[r] += a[r].x * w0;
                acc[r] += a[r].y * w1;
                acc[r] += a[r].z * w2;
                acc[r] += a[r].w * w3;
            }
        }
        __syncthreads();
    }
#pragma unroll
    for (int r = 0; r < 8; r++) {
        int row = rb + ty * 8 + r;
        if (row < NN) O[(size_t)row * HD + tx] = acc[r];
    }
}

// ---------------------------------------------------------------------------
// CSR gather: 16 threads/node (one float4 lane each), self-loop+bias+relu fused.
__global__ void __launch_bounds__(256) k_gather(const float* __restrict__ t,
                                                float* __restrict__ h,
                                                const float* __restrict__ b,
                                                int relu) {
    int node = blockIdx.x * 16 + (threadIdx.x >> 4);
    int q = threadIdx.x & 15;
    if (node >= NN) return;
    const float4* tv = (const float4*)t;

    float di = g_dinv[node];
    float4 sv = tv[(size_t)node * 16 + q];
    float di2 = di * di;
    float4 acc = make_float4(sv.x * di2, sv.y * di2, sv.z * di2, sv.w * di2);

    int beg = g_off[node], end = g_off[node + 1];
    for (int i = beg; i < end; i++) {
        int s = __ldg(&g_csr[i]);
        float nm = __ldg(&g_enorm[i]);
        float4 v = tv[(size_t)s * 16 + q];
        acc.x += nm * v.x;
        acc.y += nm * v.y;
        acc.z += nm * v.z;
        acc.w += nm * v.w;
    }
    float4 bb = ((const float4*)b)[q];
    acc.x += bb.x; acc.y += bb.y; acc.z += bb.z; acc.w += bb.w;
    if (relu) {
        acc.x = fmaxf(acc.x, 0.f);
        acc.y = fmaxf(acc.y, 0.f);
        acc.z = fmaxf(acc.z, 0.f);
        acc.w = fmaxf(acc.w, 0.f);
    }
    ((float4*)h)[(size_t)node * 16 + q] = acc;
}

// ---------------------------------------------------------------------------
// Row L2-normalize -> g_hn (float4) AND out_h (scalar; view is 4B-aligned only)
__global__ void k_norm(const float* __restrict__ h, float* __restrict__ oh,
                       float* __restrict__ out_h) {
    int n = blockIdx.x * blockDim.x + threadIdx.x;
    if (n >= NN) return;
    const float4* hv = (const float4*)(h + (size_t)n * HD);
    float4 r[16];
    float ss = 0.f;
#pragma unroll
    for (int i = 0; i < 16; i++) {
        float4 v = hv[i];
        r[i] = v;
        ss += v.x * v.x + v.y * v.y + v.z * v.z + v.w * v.w;
    }
    float sc = 1.0f / fmaxf(sqrtf(ss), 1e-12f);
    float4* ov = (float4*)(oh + (size_t)n * HD);
    float* oo = out_h + (size_t)n * HD;
#pragma unroll
    for (int i = 0; i < 16; i++) {
        float4 v = r[i];
        v.x *= sc; v.y *= sc; v.z *= sc; v.w *= sc;
        ov[i] = v;
        oo[i * 4 + 0] = v.x;
        oo[i * 4 + 1] = v.y;
        oo[i * 4 + 2] = v.z;
        oo[i * 4 + 3] = v.w;
    }
}

// logits = hn @ W3 + b3 ; log_softmax (thread per row, W3 in smem)
__global__ void k_pred(const float* __restrict__ hn, const float* __restrict__ W3,
                       const float* __restrict__ b3, float* __restrict__ pred) {
    __shared__ float sW[HD * CD];
    __shared__ float sb[CD];
    for (int i = threadIdx.x; i < HD * CD; i += blockDim.x) sW[i] = W3[i];
    if (threadIdx.x < CD) sb[threadIdx.x] = b3[threadIdx.x];
    __syncthreads();
    int n = blockIdx.x * blockDim.x + threadIdx.x;
    if (n >= NN) return;
    float z[CD];
#pragma unroll
    for (int c = 0; c < CD; c++) z[c] = sb[c];
    const float4* hv = (const float4*)(hn + (size_t)n * HD);
#pragma unroll
    for (int k4 = 0; k4 < 16; k4++) {
        float4 v = hv[k4];
        const float* w0 = &sW[(k4 * 4 + 0) * CD];
        const float* w1 = &sW[(k4 * 4 + 1) * CD];
        const float* w2 = &sW[(k4 * 4 + 2) * CD];
        const float* w3 = &sW[(k4 * 4 + 3) * CD];
#pragma unroll
        for (int c = 0; c < CD; c++)
            z[c] += v.x * w0[c] + v.y * w1[c] + v.z * w2[c] + v.w * w3[c];
    }
    float m = z[0];
#pragma unroll
    for (int c = 1; c < CD; c++) m = fmaxf(m, z[c]);
    float se = 0.f;
#pragma unroll
    for (int c = 0; c < CD; c++) se += expf(z[c] - m);
    float lse = m + logf(se);
    float* po = pred + (size_t)n * CD;   // scalar stores: 4B alignment OK
#pragma unroll
    for (int c = 0; c < CD; c++) po[c] = z[c] - lse;
}

// NLL loss over train indices — single block, deterministic reduce
__global__ void k_loss(const float* __restrict__ pred, const int* __restrict__ labels,
                       const int* __restrict__ tidx, float* __restrict__ out) {
    __shared__ float sred[256];
    float s = 0.f;
    for (int i = threadIdx.x; i < NTR; i += 256) {
        int idx = tidx[i];
        s += pred[(size_t)idx * CD + labels[idx]];
    }
    sred[threadIdx.x] = s;
    __syncthreads();
    for (int o = 128; o > 0; o >>= 1) {
        if (threadIdx.x < o) sred[threadIdx.x] += sred[threadIdx.x + o];
        __syncthreads();
    }
    if (threadIdx.x == 0) out[0] = -sred[0] / (float)NTR;
}

// ---------------------------------------------------------------------------
extern "C" void kernel_launch(void* const* d_in, const int* in_sizes, int n_in,
                              void* d_out, int out_size) {
    const float* feats  = (const float*)d_in[0];
    const float* W1     = (const float*)d_in[1];
    const float* b1     = (const float*)d_in[2];
    const float* W2     = (const float*)d_in[3];
    const float* b2     = (const float*)d_in[4];
    const float* W3     = (const float*)d_in[5];
    const float* b3     = (const float*)d_in[6];
    const int*   edges  = (const int*)d_in[7];
    const int*   labels = (const int*)d_in[8];
    const int*   tidx   = (const int*)d_in[9];

    float* out      = (float*)d_out;
    float* out_pred = out + 1;
    float* out_h    = out + 1 + (size_t)NN * CD;

    float* t_ptr;  cudaGetSymbolAddress((void**)&t_ptr, g_t);
    float* h_ptr;  cudaGetSymbolAddress((void**)&h_ptr, g_h);
    float* hn_ptr; cudaGetSymbolAddress((void**)&hn_ptr, g_hn);
    int*   deg_ptr; cudaGetSymbolAddress((void**)&deg_ptr, g_deg);

    const int* src = edges;        // edge_list[0]
    const int* dst = edges + EE;   // edge_list[1]

    // ---- CSR build (per call; deterministic up to fp-irrelevant bucket order)
    k_zero_i<<<(NN + 255) / 256, 256>>>(deg_ptr, NN);
    k_deg<<<(EE + 255) / 256, 256>>>(dst);
    k_dinv<<<(NN + 255) / 256, 256>>>();
    k_scan<<<1, 1024>>>();
    k_fill<<<(EE + 255) / 256, 256>>>(src, dst);

    const int gemm_blocks = (NN + 15) / 16;
    const int gath_blocks = (NN + 15) / 16;

    // Layer 0: feats -> h0  (no relu)
    k_gemm<IND><<<gemm_blocks, 128>>>(feats, W1, t_ptr);
    k_gather<<<gath_blocks, 256>>>(t_ptr, h_ptr, b1, 0);

    // Hidden layers (relu)
    for (int l = 0; l < 2; l++) {
        k_gemm<HD><<<gemm_blocks, 128>>>(h_ptr, W2 + (size_t)l * HD * HD, t_ptr);
        k_gather<<<gath_blocks, 256>>>(t_ptr, h_ptr, b2 + (size_t)l * HD, 1);
    }

    // normalize -> g_hn + out_h ; logits + log_softmax -> out_pred ; nll -> out[0]
    k_norm<<<(NN + 255) / 256, 256>>>(h_ptr, hn_ptr, out_h);
    k_pred<<<(NN + 255) / 256, 256>>>(hn_ptr, W3, b3, out_pred);
    k_loss<<<1, 256>>>(out_pred, labels, tidx, out);
}

// round 7
// speedup vs baseline: 1.4952x; 1.2189x over previous
#include <cuda_runtime.h>
#include <math.h>

#define NN   50000
#define EE   1600000
#define IND  256
#define HD   64
#define CD   16
#define NTR  5000
#define NH   (NN*HD)
#define SCB  ((NN + 255) / 256)   // 196 scan blocks

// Scratch (no allocs allowed) — all 16B aligned where float4-accessed.
__device__ __align__(16) float g_t[NH];        // x @ W  (transformed features)
__device__ __align__(16) float g_h[NH];        // layer output
__device__ __align__(16) float g_hn[NH];       // L2-normalized h
__device__ float g_dinv[NN];                   // D^{-1/2} including self-loop
__device__ int   g_deg[NN];                    // edge-only indegree
__device__ int   g_off[NN + 1];                // CSR offsets
__device__ int   g_cur[NN];                    // fill cursors
__device__ int   g_bsum[SCB];                  // per-block degree sums
__device__ int   g_csr[EE];                    // src ids, grouped by dst
__device__ float g_enorm[EE];                  // dinv[src]*dinv[dst], CSR order

// ---------------------------------------------------------------------------
__global__ void k_zero_i(int* p, int n) {
    int i = blockIdx.x * blockDim.x + threadIdx.x;
    if (i < n) p[i] = 0;
}
__global__ void k_deg(const int* __restrict__ dst) {
    int e = blockIdx.x * blockDim.x + threadIdx.x;
    if (e < EE) atomicAdd(&g_deg[dst[e]], 1);
}
__global__ void k_dinv() {
    int i = blockIdx.x * blockDim.x + threadIdx.x;
    if (i < NN) g_dinv[i] = rsqrtf((float)g_deg[i] + 1.0f);  // +1 self-loop
}

// ---- 3-phase device-wide exclusive scan of g_deg -> g_off / g_cur ---------
// Phase A: per-block exclusive scan, write partials to g_off, sums to g_bsum.
__global__ void k_scanA() {
    __shared__ int ss[256];
    int t = threadIdx.x;
    int idx = blockIdx.x * 256 + t;
    int d = (idx < NN) ? g_deg[idx] : 0;
    ss[t] = d;
    __syncthreads();
    int inc = d;
#pragma unroll
    for (int o = 1; o < 256; o <<= 1) {
        int v = (t >= o) ? ss[t - o] : 0;
        __syncthreads();
        ss[t] += v;
        __syncthreads();
    }
    inc = ss[t];
    if (idx < NN) g_off[idx] = inc - d;      // block-local exclusive
    if (t == 255) g_bsum[blockIdx.x] = inc;  // block total
}
// Phase B: single block scans the block sums (exclusive, in place).
__global__ void k_scanB() {
    __shared__ int ss[SCB];
    int t = threadIdx.x;
    int v = (t < SCB) ? g_bsum[t] : 0;
    if (t < SCB) ss[t] = v;
    __syncthreads();
    for (int o = 1; o < SCB; o <<= 1) {
        int u = (t >= o && t < SCB) ? ss[t - o] : 0;
        __syncthreads();
        if (t < SCB) ss[t] += u;
        __syncthreads();
    }
    if (t < SCB) g_bsum[t] = ss[t] - v;      // exclusive
}
// Phase C: add block offsets; init cursors; g_off[NN] = EE (deg sums to EE).
__global__ void k_scanC() {
    int idx = blockIdx.x * 256 + threadIdx.x;
    if (idx < NN) {
        int o = g_off[idx] + g_bsum[blockIdx.x];
        g_off[idx] = o;
        g_cur[idx] = o;
    }
    if (idx == 0) g_off[NN] = EE;
}

// Bucket edges by dst; store src id and precomputed symmetric norm.
__global__ void k_fill(const int* __restrict__ src, const int* __restrict__ dst) {
    int e = blockIdx.x * blockDim.x + threadIdx.x;
    if (e >= EE) return;
    int s = src[e], d = dst[e];
    int pos = atomicAdd(&g_cur[d], 1);
    g_csr[pos] = s;
    g_enorm[pos] = g_dinv[s] * g_dinv[d];
}

// ---------------------------------------------------------------------------
// O[N,64] = A[N,K] @ W[K,64].  128 threads, 16 rows/block, K chunked by 64.
template <int K>
__global__ void __launch_bounds__(128) k_gemm(const float* __restrict__ A,
                                              const float* __restrict__ W,
                                              float* __restrict__ O) {
    __shared__ float4 sA[16][16];   // 16 rows x 64 k-floats
    __shared__ float  sW[64][64];   // 64 k x 64 cols
    const int tx = threadIdx.x & 63;   // output column
    const int ty = threadIdx.x >> 6;   // row group (0/1)
    const int rb = blockIdx.x * 16;

    float acc[8] = {0.f, 0.f, 0.f, 0.f, 0.f, 0.f, 0.f, 0.f};

    for (int kc = 0; kc < K; kc += 64) {
        for (int i = threadIdx.x; i < 256; i += 128) {
            int r = i >> 4, c4 = i & 15;
            int row = rb + r;
            sA[r][c4] = (row < NN)
                ? ((const float4*)(A + (size_t)row * K + kc))[c4]
                : make_float4(0.f, 0.f, 0.f, 0.f);
        }
        const float4* Wv = (const float4*)(W + (size_t)kc * HD);
        for (int i = threadIdx.x; i < 1024; i += 128) {
            ((float4*)&sW[0][0])[i] = Wv[i];
        }
        __syncthreads();
#pragma unroll
        for (int k4 = 0; k4 < 16; k4++) {
            float4 a[8];
#pragma unroll
            for (int r = 0; r < 8; r++) a[r] = sA[ty * 8 + r][k4];
            float w0 = sW[k4 * 4 + 0][tx];
            float w1 = sW[k4 * 4 + 1][tx];
            float w2 = sW[k4 * 4 + 2][tx];
            float w3 = sW[k4 * 4 + 3][tx];
#pragma unroll
            for (int r = 0; r < 8; r++) {
                acc[r] += a[r].x * w0;
                acc[r] += a[r].y * w1;
                acc[r] += a[r].z * w2;
                acc[r] += a[r].w * w3;
            }
        }
        __syncthreads();
    }
#pragma unroll
    for (int r = 0; r < 8; r++) {
        int row = rb + ty * 8 + r;
        if (row < NN) O[(size_t)row * HD + tx] = acc[r];
    }
}

// ---------------------------------------------------------------------------
// CSR gather: 16 threads/node (one float4 lane each), self-loop+bias+relu fused.
__global__ void __launch_bounds__(256) k_gather(const float* __restrict__ t,
                                                float* __restrict__ h,
                                                const float* __restrict__ b,
                                                int relu) {
    int node = blockIdx.x * 16 + (threadIdx.x >> 4);
    int q = threadIdx.x & 15;
    if (node >= NN) return;
    const float4* tv = (const float4*)t;

    float di = g_dinv[node];
    float4 sv = tv[(size_t)node * 16 + q];
    float di2 = di * di;
    float4 acc = make_float4(sv.x * di2, sv.y * di2, sv.z * di2, sv.w * di2);

    int beg = g_off[node], end = g_off[node + 1];
    for (int i = beg; i < end; i++) {
        int s = __ldg(&g_csr[i]);
        float nm = __ldg(&g_enorm[i]);
        float4 v = tv[(size_t)s * 16 + q];
        acc.x += nm * v.x;
        acc.y += nm * v.y;
        acc.z += nm * v.z;
        acc.w += nm * v.w;
    }
    float4 bb = ((const float4*)b)[q];
    acc.x += bb.x; acc.y += bb.y; acc.z += bb.z; acc.w += bb.w;
    if (relu) {
        acc.x = fmaxf(acc.x, 0.f);
        acc.y = fmaxf(acc.y, 0.f);
        acc.z = fmaxf(acc.z, 0.f);
        acc.w = fmaxf(acc.w, 0.f);
    }
    ((float4*)h)[(size_t)node * 16 + q] = acc;
}

// ---------------------------------------------------------------------------
// Row L2-normalize -> g_hn (float4) AND out_h (scalar; view is 4B-aligned only)
__global__ void k_norm(const float* __restrict__ h, float* __restrict__ oh,
                       float* __restrict__ out_h) {
    int n = blockIdx.x * blockDim.x + threadIdx.x;
    if (n >= NN) return;
    const float4* hv = (const float4*)(h + (size_t)n * HD);
    float4 r[16];
    float ss = 0.f;
#pragma unroll
    for (int i = 0; i < 16; i++) {
        float4 v = hv[i];
        r[i] = v;
        ss += v.x * v.x + v.y * v.y + v.z * v.z + v.w * v.w;
    }
    float sc = 1.0f / fmaxf(sqrtf(ss), 1e-12f);
    float4* ov = (float4*)(oh + (size_t)n * HD);
    float* oo = out_h + (size_t)n * HD;
#pragma unroll
    for (int i = 0; i < 16; i++) {
        float4 v = r[i];
        v.x *= sc; v.y *= sc; v.z *= sc; v.w *= sc;
        ov[i] = v;
        oo[i * 4 + 0] = v.x;
        oo[i * 4 + 1] = v.y;
        oo[i * 4 + 2] = v.z;
        oo[i * 4 + 3] = v.w;
    }
}

// logits = hn @ W3 + b3 ; log_softmax (thread per row, W3 in smem)
__global__ void k_pred(const float* __restrict__ hn, const float* __restrict__ W3,
                       const float* __restrict__ b3, float* __restrict__ pred) {
    __shared__ float sW[HD * CD];
    __shared__ float sb[CD];
    for (int i = threadIdx.x; i < HD * CD; i += blockDim.x) sW[i] = W3[i];
    if (threadIdx.x < CD) sb[threadIdx.x] = b3[threadIdx.x];
    __syncthreads();
    int n = blockIdx.x * blockDim.x + threadIdx.x;
    if (n >= NN) return;
    float z[CD];
#pragma unroll
    for (int c = 0; c < CD; c++) z[c] = sb[c];
    const float4* hv = (const float4*)(hn + (size_t)n * HD);
#pragma unroll
    for (int k4 = 0; k4 < 16; k4++) {
        float4 v = hv[k4];
        const float* w0 = &sW[(k4 * 4 + 0) * CD];
        const float* w1 = &sW[(k4 * 4 + 1) * CD];
        const float* w2 = &sW[(k4 * 4 + 2) * CD];
        const float* w3 = &sW[(k4 * 4 + 3) * CD];
#pragma unroll
        for (int c = 0; c < CD; c++)
            z[c] += v.x * w0[c] + v.y * w1[c] + v.z * w2[c] + v.w * w3[c];
    }
    float m = z[0];
#pragma unroll
    for (int c = 1; c < CD; c++) m = fmaxf(m, z[c]);
    float se = 0.f;
#pragma unroll
    for (int c = 0; c < CD; c++) se += expf(z[c] - m);
    float lse = m + logf(se);
    float* po = pred + (size_t)n * CD;   // scalar stores: 4B alignment OK
#pragma unroll
    for (int c = 0; c < CD; c++) po[c] = z[c] - lse;
}

// NLL loss over train indices — single block, deterministic reduce
__global__ void k_loss(const float* __restrict__ pred, const int* __restrict__ labels,
                       const int* __restrict__ tidx, float* __restrict__ out) {
    __shared__ float sred[256];
    float s = 0.f;
    for (int i = threadIdx.x; i < NTR; i += 256) {
        int idx = tidx[i];
        s += pred[(size_t)idx * CD + labels[idx]];
    }
    sred[threadIdx.x] = s;
    __syncthreads();
    for (int o = 128; o > 0; o >>= 1) {
        if (threadIdx.x < o) sred[threadIdx.x] += sred[threadIdx.x + o];
        __syncthreads();
    }
    if (threadIdx.x == 0) out[0] = -sred[0] / (float)NTR;
}

// ---------------------------------------------------------------------------
extern "C" void kernel_launch(void* const* d_in, const int* in_sizes, int n_in,
                              void* d_out, int out_size) {
    const float* feats  = (const float*)d_in[0];
    const float* W1     = (const float*)d_in[1];
    const float* b1     = (const float*)d_in[2];
    const float* W2     = (const float*)d_in[3];
    const float* b2     = (const float*)d_in[4];
    const float* W3     = (const float*)d_in[5];
    const float* b3     = (const float*)d_in[6];
    const int*   edges  = (const int*)d_in[7];
    const int*   labels = (const int*)d_in[8];
    const int*   tidx   = (const int*)d_in[9];

    float* out      = (float*)d_out;
    float* out_pred = out + 1;
    float* out_h    = out + 1 + (size_t)NN * CD;

    float* t_ptr;  cudaGetSymbolAddress((void**)&t_ptr, g_t);
    float* h_ptr;  cudaGetSymbolAddress((void**)&h_ptr, g_h);
    float* hn_ptr; cudaGetSymbolAddress((void**)&hn_ptr, g_hn);
    int*   deg_ptr; cudaGetSymbolAddress((void**)&deg_ptr, g_deg);

    const int* src = edges;        // edge_list[0]
    const int* dst = edges + EE;   // edge_list[1]

    // ---- CSR build
    k_zero_i<<<(NN + 255) / 256, 256>>>(deg_ptr, NN);
    k_deg<<<(EE + 255) / 256, 256>>>(dst);
    k_dinv<<<(NN + 255) / 256, 256>>>();
    k_scanA<<<SCB, 256>>>();
    k_scanB<<<1, 256>>>();
    k_scanC<<<SCB, 256>>>();
    k_fill<<<(EE + 255) / 256, 256>>>(src, dst);

    const int gemm_blocks = (NN + 15) / 16;
    const int gath_blocks = (NN + 15) / 16;

    // Layer 0: feats -> h0  (no relu)
    k_gemm<IND><<<gemm_blocks, 128>>>(feats, W1, t_ptr);
    k_gather<<<gath_blocks, 256>>>(t_ptr, h_ptr, b1, 0);

    // Hidden layers (relu)
    for (int l = 0; l < 2; l++) {
        k_gemm<HD><<<gemm_blocks, 128>>>(h_ptr, W2 + (size_t)l * HD * HD, t_ptr);
        k_gather<<<gath_blocks, 256>>>(t_ptr, h_ptr, b2 + (size_t)l * HD, 1);
    }

    // normalize -> g_hn + out_h ; logits + log_softmax -> out_pred ; nll -> out[0]
    k_norm<<<(NN + 255) / 256, 256>>>(h_ptr, hn_ptr, out_h);
    k_pred<<<(NN + 255) / 256, 256>>>(hn_ptr, W3, b3, out_pred);
    k_loss<<<1, 256>>>(out_pred, labels, tidx, out);
}